// round 11
// baseline (speedup 1.0000x reference)
#include <cuda_runtime.h>
#include <cstdint>

typedef unsigned long long ull;

#define HH 200
#define WW 272
#define SP 54400
#define NANCH 489600
#define PRE_NMSN 6000
#define POST_NMSN 1000
#define CAND_MAX 8192
#define MASKW 96
#define NMS_TH 0.7f

// ---------------- scratch ----------------
__device__ float g_x[(size_t)256 * SP];
__device__ float g_wr[9 * 256 * 256];
__device__ float g_conf[NANCH];
__device__ float g_reg[(size_t)SP * 36];
__device__ unsigned g_hist[256];
__device__ unsigned g_prefix;
__device__ int g_krem;
__device__ int g_candCnt;
__device__ ull g_cand[CAND_MAX];
__device__ float4 g_boxes[PRE_NMSN];
__device__ ull g_validmask[MASKW];
__device__ ull g_mask[(size_t)PRE_NMSN * MASKW];
__device__ int g_keptIdx[POST_NMSN];
__device__ int g_keptCnt;

// ---------------- helpers ----------------
__device__ __forceinline__ ull ffma2(ull a, ull b, ull c) {
    ull d;
    asm("fma.rn.f32x2 %0, %1, %2, %3;" : "=l"(d) : "l"(a), "l"(b), "l"(c));
    return d;
}
__device__ __forceinline__ ull packdup(float x) {
    ull d; unsigned u = __float_as_uint(x);
    asm("mov.b64 %0, {%1, %1};" : "=l"(d) : "r"(u));
    return d;
}
__device__ __forceinline__ unsigned key32(float v) {
    unsigned b = __float_as_uint(v);
    return (b & 0x80000000u) ? ~b : (b | 0x80000000u);
}
__device__ __forceinline__ float read_dim(const int* p) {
    int v = *p;
    if (v > 0 && v < 1000000) return (float)v;
    return __int_as_float(v);
}

// ---------------- init ----------------
__global__ void k_init() {
    int tid = threadIdx.x;
    g_hist[tid] = 0;
    if (tid < MASKW) g_validmask[tid] = 0ull;
    if (tid == 0) { g_prefix = 0; g_krem = PRE_NMSN; g_candCnt = 0; g_keptCnt = 0; }
}

// ---------------- weight repack ----------------
__global__ void k_repack(const float* __restrict__ w1) {
    int i = blockIdx.x * 1024 + threadIdx.x;
    if (i >= 9 * 256 * 256) return;
    int co = i / 2304;
    int r = i - co * 2304;
    int c = r / 9;
    int kk = r - c * 9;
    g_wr[((kk << 8) + c) * 256 + co] = w1[i];
}

// ---------------- conv 3x3 + bias + relu ----------------
// K iterated in KCRS order: k = c*9 + (ky*3+kx), ascending, one sequential
// fp32 chain per output (bit-identical to the R8 passing kernel).
// 512 threads; per-thread 4co x 8n; double-buffered smem, 1 sync/stage.
__global__ void __launch_bounds__(512) k_conv(const float* __restrict__ feat,
                                              const float* __restrict__ bias) {
    __shared__ float As[2][8][128];   // [stage][k-row][co]
    __shared__ float Bs[2][8][128];   // [stage][k-row][n]
    const int tid = threadIdx.x;
    const int n0 = blockIdx.x * 128, co0 = blockIdx.y * 128;

    // loader mapping: row r = tid>>6 (0..7), col = (tid&63)*2 (2 consecutive)
    const int lrr = tid >> 6;
    const int lcol = (tid & 63) << 1;
    // compute mapping: nt = tid&15 -> 8 n's;  ct = tid>>4 -> 4 co's
    const int n8 = (tid & 15) << 3;
    const int co4 = (tid >> 4) << 2;

    // fixed geometry for the 2 loader columns
    int nA = n0 + lcol, nB = n0 + lcol + 1;
    int yA = nA / WW, xA = nA - yA * WW;
    int yB = nB / WW, xB = nB - yB * WW;

    ull acc[4][4];
#pragma unroll
    for (int j = 0; j < 4; j++)
#pragma unroll
        for (int p = 0; p < 4; p++) acc[j][p] = 0ull;

    float2 wv; float f0, f1;
#define CONV_LD(q) { \
        int kq = ((q) << 3) + lrr; \
        int c = kq / 9; int kk = kq - c * 9; \
        int kd = kk / 3; int dy = kd - 1, dx = kk - kd * 3 - 1; \
        wv = *(const float2*)(g_wr + ((kk << 8) + c) * 256 + co0 + lcol); \
        const float* fp = feat + (size_t)c * SP + dy * WW + dx; \
        bool okA = ((unsigned)(yA + dy) < (unsigned)HH) && ((unsigned)(xA + dx) < (unsigned)WW); \
        bool okB = ((unsigned)(yB + dy) < (unsigned)HH) && ((unsigned)(xB + dx) < (unsigned)WW); \
        f0 = okA ? fp[nA] : 0.f; \
        f1 = okB ? fp[nB] : 0.f; \
    }

    CONV_LD(0)
    {
        *(float2*)&As[0][lrr][lcol] = wv;
        Bs[0][lrr][lcol] = f0; Bs[0][lrr][lcol + 1] = f1;
    }
    __syncthreads();

    for (int q = 0; q < 288; q++) {
        int s = q & 1;
        if (q < 287) CONV_LD(q + 1)
#pragma unroll
        for (int k8 = 0; k8 < 8; k8++) {
            float4 af = *(const float4*)&As[s][k8][co4];
            float4 b0 = *(const float4*)&Bs[s][k8][n8];
            float4 b1 = *(const float4*)&Bs[s][k8][n8 + 4];
            ull bb0 = ((const ull*)&b0)[0], bb1 = ((const ull*)&b0)[1];
            ull bb2 = ((const ull*)&b1)[0], bb3 = ((const ull*)&b1)[1];
            float a4[4] = {af.x, af.y, af.z, af.w};
#pragma unroll
            for (int j = 0; j < 4; j++) {
                ull aa = packdup(a4[j]);
                acc[j][0] = ffma2(aa, bb0, acc[j][0]);
                acc[j][1] = ffma2(aa, bb1, acc[j][1]);
                acc[j][2] = ffma2(aa, bb2, acc[j][2]);
                acc[j][3] = ffma2(aa, bb3, acc[j][3]);
            }
        }
        if (q < 287) {
            int s2 = s ^ 1;
            *(float2*)&As[s2][lrr][lcol] = wv;
            Bs[s2][lrr][lcol] = f0; Bs[s2][lrr][lcol + 1] = f1;
        }
        __syncthreads();
    }

#pragma unroll
    for (int j = 0; j < 4; j++) {
        int co = co0 + co4 + j;
        float bsv = bias[co];
        float o[8];
#pragma unroll
        for (int p = 0; p < 4; p++) {
            float lo = __uint_as_float((unsigned)(acc[j][p] & 0xffffffffull));
            float hi = __uint_as_float((unsigned)(acc[j][p] >> 32));
            o[2 * p]     = fmaxf(lo + bsv, 0.f);
            o[2 * p + 1] = fmaxf(hi + bsv, 0.f);
        }
        float* dst = g_x + (size_t)co * SP + n0 + n8;
        *(float4*)dst       = make_float4(o[0], o[1], o[2], o[3]);
        *(float4*)(dst + 4) = make_float4(o[4], o[5], o[6], o[7]);
    }
}

// ---------------- 1x1 heads (1 cell/thread, same ascending-c order) ----------------
__global__ void __launch_bounds__(256) k_heads(const float* __restrict__ wc,
                                               const float* __restrict__ bc,
                                               const float* __restrict__ wr,
                                               const float* __restrict__ br) {
    __shared__ float ws[45 * 256];
    __shared__ float bs[45];
    int tid = threadIdx.x;
    for (int i = tid; i < 45 * 256; i += 256) {
        int o = i >> 8, c = i & 255;
        ws[i] = (o < 9) ? wc[o * 256 + c] : wr[(o - 9) * 256 + c];
    }
    if (tid < 45) bs[tid] = (tid < 9) ? bc[tid] : br[tid - 9];
    __syncthreads();
    int n = blockIdx.x * 256 + tid;
    if (n >= SP) return;
    float a[45];
#pragma unroll
    for (int o = 0; o < 45; o++) a[o] = 0.f;
    for (int c0 = 0; c0 < 256; c0 += 8) {
        float xv[8];
#pragma unroll
        for (int u = 0; u < 8; u++)
            xv[u] = g_x[(size_t)(c0 + u) * SP + n];
#pragma unroll
        for (int o = 0; o < 45; o++) {
            float4 w0 = *(const float4*)&ws[o * 256 + c0];
            float4 w1 = *(const float4*)&ws[o * 256 + c0 + 4];
            a[o] += w0.x * xv[0]; a[o] += w0.y * xv[1];
            a[o] += w0.z * xv[2]; a[o] += w0.w * xv[3];
            a[o] += w1.x * xv[4]; a[o] += w1.y * xv[5];
            a[o] += w1.z * xv[6]; a[o] += w1.w * xv[7];
        }
    }
#pragma unroll
    for (int o = 0; o < 9; o++) g_conf[n * 9 + o] = a[o] + bs[o];
#pragma unroll
    for (int o = 0; o < 36; o++) g_reg[(size_t)n * 36 + o] = a[9 + o] + bs[9 + o];
}

// ---------------- radix select ----------------
__global__ void k_hist(int pass) {
    __shared__ unsigned sh[256];
    int tid = threadIdx.x;
    sh[tid] = 0;
    __syncthreads();
    unsigned pref = g_prefix;
    int sD = 24 - 8 * pass;
    for (int i = blockIdx.x * 256 + tid; i < NANCH; i += gridDim.x * 256) {
        unsigned k = key32(g_conf[i]);
        bool part = (pass == 0) || ((k >> (sD + 8)) == pref);
        if (part) atomicAdd(&sh[(k >> sD) & 255u], 1u);
    }
    __syncthreads();
    if (sh[tid]) atomicAdd(&g_hist[tid], sh[tid]);
}

__global__ void k_resolve() {
    __shared__ unsigned sh[256];
    int tid = threadIdx.x;
    sh[tid] = g_hist[tid];
    g_hist[tid] = 0;
    __syncthreads();
    if (tid == 0) {
        unsigned krem = (unsigned)g_krem;
        unsigned cum = 0; int d = 255;
        for (; d > 0; d--) {
            unsigned c = sh[d];
            if (cum + c >= krem) break;
            cum += c;
        }
        g_prefix = (g_prefix << 8) | (unsigned)d;
        g_krem = (int)(krem - cum);
    }
}

__global__ void k_compact() {
    unsigned T = g_prefix;
    for (int i = blockIdx.x * 256 + threadIdx.x; i < NANCH; i += gridDim.x * 256) {
        unsigned k = key32(g_conf[i]);
        if (k >= T) {
            int p = atomicAdd(&g_candCnt, 1);
            if (p < CAND_MAX) g_cand[p] = ((ull)k << 32) | (ull)(0xFFFFFFFFu - (unsigned)i);
        }
    }
}

// ---------------- bitonic sort desc in smem ----------------
__global__ void k_sort() {
    extern __shared__ ull s[];
    int tid = threadIdx.x;
    int cnt = g_candCnt; if (cnt > CAND_MAX) cnt = CAND_MAX;
    for (int i = tid; i < CAND_MAX; i += 1024) s[i] = (i < cnt) ? g_cand[i] : 0ull;
    __syncthreads();
    for (int k = 2; k <= CAND_MAX; k <<= 1) {
        for (int j = k >> 1; j > 0; j >>= 1) {
            for (int i = tid; i < CAND_MAX; i += 1024) {
                int ixj = i ^ j;
                if (ixj > i) {
                    ull A = s[i], B = s[ixj];
                    bool desc = ((i & k) == 0);
                    if (desc ? (A < B) : (A > B)) { s[i] = B; s[ixj] = A; }
                }
            }
            __syncthreads();
        }
    }
    for (int i = tid; i < CAND_MAX; i += 1024) g_cand[i] = s[i];
}

// ---------------- decode + clip + min-size ----------------
__global__ void k_decode(const int* __restrict__ ph, const int* __restrict__ pw) {
    int t = blockIdx.x * 128 + threadIdx.x;
    if (t >= PRE_NMSN) return;
    float IW = read_dim(pw), IH = read_dim(ph);
    ull cd = g_cand[t];
    unsigned orig = 0xFFFFFFFFu - (unsigned)(cd & 0xFFFFFFFFull);
    if (orig >= NANCH) { g_boxes[t] = make_float4(0, 0, 0, 0); return; }
    int cell = orig / 9; int a = orig - cell * 9;
    int y = cell / WW;   int x = cell - y * WW;
    int si = a / 3;      int ri = a - si * 3;
    double sc  = (si == 0) ? 32.0 : ((si == 1) ? 64.0 : 128.0);
    double rat = (ri == 0) ? 0.5  : ((ri == 1) ? 1.0  : 2.0);
    double w64 = sc * sqrt(1.0 / rat), h64 = sc * sqrt(rat);
    float cxs = ((float)x + 0.5f) * 4.f;
    float cys = ((float)y + 0.5f) * 4.f;
    float ax0 = cxs + (float)(-w64 * 0.5), ax2 = cxs + (float)(w64 * 0.5);
    float ay0 = cys + (float)(-h64 * 0.5), ay2 = cys + (float)(h64 * 0.5);
    float wa = ax2 - ax0, ha = ay2 - ay0;
    float cxa = ax0 + 0.5f * wa, cya = ay0 + 0.5f * ha;
    const float* dp = g_reg + (size_t)cell * 36 + a * 4;
    float d0 = dp[0], d1 = dp[1], d2 = dp[2], d3 = dp[3];
    float cx = d0 * wa + cxa, cy = d1 * ha + cya;
    float bw = expf(d2) * wa, bh = expf(d3) * ha;
    float X0 = cx - 0.5f * bw, Y0 = cy - 0.5f * bh;
    float X1 = cx + 0.5f * bw, Y1 = cy + 0.5f * bh;
    X0 = fminf(fmaxf(X0, 0.f), IW); X1 = fminf(fmaxf(X1, 0.f), IW);
    Y0 = fminf(fmaxf(Y0, 0.f), IH); Y1 = fminf(fmaxf(Y1, 0.f), IH);
    g_boxes[t] = make_float4(X0, Y0, X1, Y1);
    if ((X1 - X0 >= 1.0f) && (Y1 - Y0 >= 1.0f))
        atomicOr(&g_validmask[t >> 6], 1ull << (t & 63));
}

// ---------------- NMS mask ----------------
__global__ void k_mask() {
    __shared__ float4 cb[64];
    int cbk = blockIdx.x, rbk = blockIdx.y;
    int cbase = cbk * 64, rbase = rbk * 64;
    int t = threadIdx.x;
    int c = cbase + t;
    cb[t] = (c < PRE_NMSN) ? g_boxes[c] : make_float4(0, 0, 0, 0);
    __syncthreads();
    int i = rbase + t;
    if (i >= PRE_NMSN) return;
    float4 a = g_boxes[i];
    float areaA = (a.z - a.x) * (a.w - a.y);
    ull bits = 0;
    int lim = min(64, PRE_NMSN - cbase);
    for (int j = 0; j < lim; j++) {
        if (cbase + j == i) continue;
        float4 b = cb[j];
        float lx = fmaxf(a.x, b.x), ly = fmaxf(a.y, b.y);
        float rx = fminf(a.z, b.z), ry = fminf(a.w, b.w);
        float w = fmaxf(rx - lx, 0.f), h = fmaxf(ry - ly, 0.f);
        float inter = w * h;
        float areaB = (b.z - b.x) * (b.w - b.y);
        float iou = inter / (areaA + areaB - inter + 1e-9f);
        if (iou > NMS_TH) bits |= 1ull << j;
    }
    g_mask[(size_t)i * MASKW + cbk] = bits;
}

// ---------------- serial greedy scan (1 warp, depth-8 prefetch ring) ----------------
__global__ void k_scan() {
    int lane = threadIdx.x;
    ull remv[3];
#pragma unroll
    for (int k = 0; k < 3; k++) {
        int w = lane * 3 + k;
        remv[k] = (w < MASKW) ? ~g_validmask[w] : ~0ull;
    }
    ull pf[8][3];
#pragma unroll
    for (int d = 0; d < 8; d++) {
        const ull* row = g_mask + (size_t)d * MASKW + lane * 3;
        pf[d][0] = row[0]; pf[d][1] = row[1]; pf[d][2] = row[2];
    }
    int cnt = 0;
    for (int i8 = 0; i8 < PRE_NMSN; i8 += 8) {
#pragma unroll
        for (int d = 0; d < 8; d++) {
            int i = i8 + d;
            int w = i >> 6;
            int owner = w / 3, wm = w - owner * 3;
            ull myw = (wm == 0) ? remv[0] : ((wm == 1) ? remv[1] : remv[2]);
            ull word = __shfl_sync(0xffffffffu, myw, owner);
            if (!((word >> (i & 63)) & 1ull)) {
                if (cnt < POST_NMSN) { if (lane == 0) g_keptIdx[cnt] = i; }
                cnt++;
                remv[0] |= pf[d][0]; remv[1] |= pf[d][1]; remv[2] |= pf[d][2];
            }
            int nx = i + 8;
            if (nx < PRE_NMSN) {
                const ull* row = g_mask + (size_t)nx * MASKW + lane * 3;
                pf[d][0] = row[0]; pf[d][1] = row[1]; pf[d][2] = row[2];
            }
        }
        if (cnt >= POST_NMSN) break;
    }
    if (lane == 0) g_keptCnt = (cnt > POST_NMSN) ? POST_NMSN : cnt;
}

// ---------------- output ----------------
__global__ void k_out(float4* __restrict__ out) {
    int r = blockIdx.x * 256 + threadIdx.x;
    if (r >= POST_NMSN) return;
    float4 v = make_float4(0, 0, 0, 0);
    if (r < g_keptCnt) v = g_boxes[g_keptIdx[r]];
    out[r] = v;
}

// ---------------- launch ----------------
extern "C" void kernel_launch(void* const* d_in, const int* in_sizes, int n_in,
                              void* d_out, int out_size) {
    const float* feature = (const float*)d_in[0];
    const float* w1      = (const float*)d_in[1];
    const float* b1      = (const float*)d_in[2];
    const float* w_cls   = (const float*)d_in[3];
    const float* b_cls   = (const float*)d_in[4];
    const float* w_reg   = (const float*)d_in[5];
    const float* b_reg   = (const float*)d_in[6];
    const int*   ih      = (const int*)d_in[7];
    const int*   iw      = (const int*)d_in[8];

    static bool attr_set = false;
    if (!attr_set) {
        cudaFuncSetAttribute(k_sort, cudaFuncAttributeMaxDynamicSharedMemorySize, 65536);
        attr_set = true;
    }

    k_init<<<1, 256>>>();
    k_repack<<<576, 1024>>>(w1);
    k_conv<<<dim3(425, 2), 512>>>(feature, b1);
    k_heads<<<213, 256>>>(w_cls, b_cls, w_reg, b_reg);
    for (int p = 0; p < 4; p++) {
        k_hist<<<232, 256>>>(p);
        k_resolve<<<1, 256>>>();
    }
    k_compact<<<232, 256>>>();
    k_sort<<<1, 1024, 65536>>>();
    k_decode<<<47, 128>>>(ih, iw);
    k_mask<<<dim3(94, 94), 64>>>();
    k_scan<<<1, 32>>>();
    k_out<<<4, 256>>>((float4*)d_out);
}

// round 14
// speedup vs baseline: 1.5581x; 1.5581x over previous
#include <cuda_runtime.h>
#include <cstdint>

typedef unsigned long long ull;

#define HH 200
#define WW 272
#define SP 54400
#define NANCH 489600
#define PRE_NMSN 6000
#define POST_NMSN 1000
#define CAND_MAX 8192
#define MASKW 96
#define NMS_TH 0.7f

// ---------------- scratch ----------------
__device__ float g_x[(size_t)256 * SP];
__device__ float g_wr[9 * 256 * 256];
__device__ float g_conf[NANCH];
__device__ float g_reg[(size_t)SP * 36];
__device__ unsigned g_hist[256];
__device__ unsigned g_prefix;
__device__ int g_krem;
__device__ int g_candCnt;
__device__ ull g_cand[CAND_MAX];
__device__ float4 g_boxes[PRE_NMSN];
__device__ ull g_validmask[MASKW];
__device__ ull g_mask[(size_t)PRE_NMSN * MASKW];
__device__ int g_keptIdx[POST_NMSN];
__device__ int g_keptCnt;

// ---------------- helpers ----------------
__device__ __forceinline__ ull ffma2(ull a, ull b, ull c) {
    ull d;
    asm("fma.rn.f32x2 %0, %1, %2, %3;" : "=l"(d) : "l"(a), "l"(b), "l"(c));
    return d;
}
__device__ __forceinline__ ull packdup(float x) {
    ull d; unsigned u = __float_as_uint(x);
    asm("mov.b64 %0, {%1, %1};" : "=l"(d) : "r"(u));
    return d;
}
__device__ __forceinline__ unsigned key32(float v) {
    unsigned b = __float_as_uint(v);
    return (b & 0x80000000u) ? ~b : (b | 0x80000000u);
}
__device__ __forceinline__ float read_dim(const int* p) {
    int v = *p;
    if (v > 0 && v < 1000000) return (float)v;
    return __int_as_float(v);
}

// ---------------- init ----------------
__global__ void k_init() {
    int tid = threadIdx.x;
    g_hist[tid] = 0;
    if (tid < MASKW) g_validmask[tid] = 0ull;
    if (tid == 0) { g_prefix = 0; g_krem = PRE_NMSN; g_candCnt = 0; g_keptCnt = 0; }
}

// ---------------- weight repack ----------------
__global__ void k_repack(const float* __restrict__ w1) {
    int i = blockIdx.x * 1024 + threadIdx.x;
    if (i >= 9 * 256 * 256) return;
    int co = i / 2304;
    int r = i - co * 2304;
    int c = r / 9;
    int kk = r - c * 9;
    g_wr[((kk << 8) + c) * 256 + co] = w1[i];
}

// ---------------- conv 3x3 + bias + relu ----------------
// K in KCRS order: k = c*9 + (ky*3+kx), ascending; one sequential fp32 chain
// per output (bit-identical numerics to the R8/R11 passing kernels).
// 256 threads; per-thread 8co x 16n; tile 128co x 256n; double-buffered smem.
__global__ void __launch_bounds__(256, 1) k_conv(const float* __restrict__ feat,
                                                 const float* __restrict__ bias) {
    __shared__ float As[2][8][128];   // [stage][k-row][co]
    __shared__ float Bs[2][8][256];   // [stage][k-row][n]
    const int tid = threadIdx.x;
    const int n0 = blockIdx.x * 256, co0 = blockIdx.y * 128;

    // loader mapping
    const int lr  = tid >> 5;          // k-row 0..7
    const int lwc = (tid & 31) << 2;   // weight col (float4)
    const int lbc = (tid & 31) << 3;   // B col base (8 floats)
    // compute mapping
    const int tn4 = (tid & 15) << 2;   // n base within each 64-seg
    const int co8 = (tid >> 4) << 3;   // 8 co per thread

    // loader geometry for 8 consecutive n
    const int nb = n0 + lbc;
    int yy[8], xx[8];
#pragma unroll
    for (int u = 0; u < 8; u++) {
        int n = nb + u;
        yy[u] = n / WW; xx[u] = n - yy[u] * WW;
    }

    ull acc[8][8];  // [co j][n pair p]: pair p covers n = (p>>1)*64 + tn4 + (p&1)*2
#pragma unroll
    for (int j = 0; j < 8; j++)
#pragma unroll
        for (int p = 0; p < 8; p++) acc[j][p] = 0ull;

    float4 wv; float fv[8];
#define CONV_LD(q) { \
        int kq = ((q) << 3) + lr; \
        int c = kq / 9; int kk = kq - c * 9; \
        int kd = kk / 3; int dy = kd - 1, dx = kk - kd * 3 - 1; \
        wv = *(const float4*)(g_wr + ((kk << 8) + c) * 256 + co0 + lwc); \
        const float* fp = feat + (size_t)c * SP + dy * WW + dx; \
        _Pragma("unroll") \
        for (int u_ = 0; u_ < 8; u_++) { \
            bool ok = ((unsigned)(yy[u_] + dy) < (unsigned)HH) && ((unsigned)(xx[u_] + dx) < (unsigned)WW); \
            fv[u_] = ok ? fp[nb + u_] : 0.f; \
        } \
    }

    CONV_LD(0)
    {
        *(float4*)&As[0][lr][lwc] = wv;
        *(float4*)&Bs[0][lr][lbc]     = make_float4(fv[0], fv[1], fv[2], fv[3]);
        *(float4*)&Bs[0][lr][lbc + 4] = make_float4(fv[4], fv[5], fv[6], fv[7]);
    }
    __syncthreads();

    for (int q = 0; q < 288; q++) {
        int s = q & 1;
        if (q < 287) CONV_LD(q + 1)
#pragma unroll
        for (int k8 = 0; k8 < 8; k8++) {
            float4 a0 = *(const float4*)&As[s][k8][co8];
            float4 a1 = *(const float4*)&As[s][k8][co8 + 4];
            ull b[8];
#pragma unroll
            for (int seg = 0; seg < 4; seg++) {
                float4 bv = *(const float4*)&Bs[s][k8][seg * 64 + tn4];
                b[2 * seg]     = ((const ull*)&bv)[0];
                b[2 * seg + 1] = ((const ull*)&bv)[1];
            }
            float a[8] = {a0.x, a0.y, a0.z, a0.w, a1.x, a1.y, a1.z, a1.w};
#pragma unroll
            for (int j = 0; j < 8; j++) {
                ull aa = packdup(a[j]);
#pragma unroll
                for (int p = 0; p < 8; p++)
                    acc[j][p] = ffma2(aa, b[p], acc[j][p]);
            }
        }
        if (q < 287) {
            int s2 = s ^ 1;
            *(float4*)&As[s2][lr][lwc] = wv;
            *(float4*)&Bs[s2][lr][lbc]     = make_float4(fv[0], fv[1], fv[2], fv[3]);
            *(float4*)&Bs[s2][lr][lbc + 4] = make_float4(fv[4], fv[5], fv[6], fv[7]);
        }
        __syncthreads();
    }

#pragma unroll
    for (int j = 0; j < 8; j++) {
        int co = co0 + co8 + j;
        float bsv = bias[co];
#pragma unroll
        for (int seg = 0; seg < 4; seg++) {
            int n = n0 + seg * 64 + tn4;
            if (n < SP) {
                ull p0 = acc[j][2 * seg], p1 = acc[j][2 * seg + 1];
                float o0 = fmaxf(__uint_as_float((unsigned)(p0 & 0xffffffffull)) + bsv, 0.f);
                float o1 = fmaxf(__uint_as_float((unsigned)(p0 >> 32)) + bsv, 0.f);
                float o2 = fmaxf(__uint_as_float((unsigned)(p1 & 0xffffffffull)) + bsv, 0.f);
                float o3 = fmaxf(__uint_as_float((unsigned)(p1 >> 32)) + bsv, 0.f);
                *(float4*)(g_x + (size_t)co * SP + n) = make_float4(o0, o1, o2, o3);
            }
        }
    }
}

// ---------------- 1x1 heads (1 cell/thread, ascending-c order) ----------------
__global__ void __launch_bounds__(256) k_heads(const float* __restrict__ wc,
                                               const float* __restrict__ bc,
                                               const float* __restrict__ wr,
                                               const float* __restrict__ br) {
    __shared__ float ws[45 * 256];
    __shared__ float bs[45];
    int tid = threadIdx.x;
    for (int i = tid; i < 45 * 256; i += 256) {
        int o = i >> 8, c = i & 255;
        ws[i] = (o < 9) ? wc[o * 256 + c] : wr[(o - 9) * 256 + c];
    }
    if (tid < 45) bs[tid] = (tid < 9) ? bc[tid] : br[tid - 9];
    __syncthreads();
    int n = blockIdx.x * 256 + tid;
    if (n >= SP) return;
    float a[45];
#pragma unroll
    for (int o = 0; o < 45; o++) a[o] = 0.f;
    for (int c0 = 0; c0 < 256; c0 += 8) {
        float xv[8];
#pragma unroll
        for (int u = 0; u < 8; u++)
            xv[u] = g_x[(size_t)(c0 + u) * SP + n];
#pragma unroll
        for (int o = 0; o < 45; o++) {
            float4 w0 = *(const float4*)&ws[o * 256 + c0];
            float4 w1 = *(const float4*)&ws[o * 256 + c0 + 4];
            a[o] += w0.x * xv[0]; a[o] += w0.y * xv[1];
            a[o] += w0.z * xv[2]; a[o] += w0.w * xv[3];
            a[o] += w1.x * xv[4]; a[o] += w1.y * xv[5];
            a[o] += w1.z * xv[6]; a[o] += w1.w * xv[7];
        }
    }
#pragma unroll
    for (int o = 0; o < 9; o++) g_conf[n * 9 + o] = a[o] + bs[o];
#pragma unroll
    for (int o = 0; o < 36; o++) g_reg[(size_t)n * 36 + o] = a[9 + o] + bs[9 + o];
}

// ---------------- radix select ----------------
__global__ void k_hist(int pass) {
    __shared__ unsigned sh[256];
    int tid = threadIdx.x;
    sh[tid] = 0;
    __syncthreads();
    unsigned pref = g_prefix;
    int sD = 24 - 8 * pass;
    for (int i = blockIdx.x * 256 + tid; i < NANCH; i += gridDim.x * 256) {
        unsigned k = key32(g_conf[i]);
        bool part = (pass == 0) || ((k >> (sD + 8)) == pref);
        if (part) atomicAdd(&sh[(k >> sD) & 255u], 1u);
    }
    __syncthreads();
    if (sh[tid]) atomicAdd(&g_hist[tid], sh[tid]);
}

__global__ void k_resolve() {
    __shared__ unsigned sh[256];
    int tid = threadIdx.x;
    sh[tid] = g_hist[tid];
    g_hist[tid] = 0;
    __syncthreads();
    if (tid == 0) {
        unsigned krem = (unsigned)g_krem;
        unsigned cum = 0; int d = 255;
        for (; d > 0; d--) {
            unsigned c = sh[d];
            if (cum + c >= krem) break;
            cum += c;
        }
        g_prefix = (g_prefix << 8) | (unsigned)d;
        g_krem = (int)(krem - cum);
    }
}

__global__ void k_compact() {
    unsigned T = g_prefix;
    for (int i = blockIdx.x * 256 + threadIdx.x; i < NANCH; i += gridDim.x * 256) {
        unsigned k = key32(g_conf[i]);
        if (k >= T) {
            int p = atomicAdd(&g_candCnt, 1);
            if (p < CAND_MAX) g_cand[p] = ((ull)k << 32) | (ull)(0xFFFFFFFFu - (unsigned)i);
        }
    }
}

// ---------------- bitonic sort desc in smem ----------------
__global__ void k_sort() {
    extern __shared__ ull s[];
    int tid = threadIdx.x;
    int cnt = g_candCnt; if (cnt > CAND_MAX) cnt = CAND_MAX;
    for (int i = tid; i < CAND_MAX; i += 1024) s[i] = (i < cnt) ? g_cand[i] : 0ull;
    __syncthreads();
    for (int k = 2; k <= CAND_MAX; k <<= 1) {
        for (int j = k >> 1; j > 0; j >>= 1) {
            for (int i = tid; i < CAND_MAX; i += 1024) {
                int ixj = i ^ j;
                if (ixj > i) {
                    ull A = s[i], B = s[ixj];
                    bool desc = ((i & k) == 0);
                    if (desc ? (A < B) : (A > B)) { s[i] = B; s[ixj] = A; }
                }
            }
            __syncthreads();
        }
    }
    for (int i = tid; i < CAND_MAX; i += 1024) g_cand[i] = s[i];
}

// ---------------- decode + clip + min-size ----------------
__global__ void k_decode(const int* __restrict__ ph, const int* __restrict__ pw) {
    int t = blockIdx.x * 128 + threadIdx.x;
    if (t >= PRE_NMSN) return;
    float IW = read_dim(pw), IH = read_dim(ph);
    ull cd = g_cand[t];
    unsigned orig = 0xFFFFFFFFu - (unsigned)(cd & 0xFFFFFFFFull);
    if (orig >= NANCH) { g_boxes[t] = make_float4(0, 0, 0, 0); return; }
    int cell = orig / 9; int a = orig - cell * 9;
    int y = cell / WW;   int x = cell - y * WW;
    int si = a / 3;      int ri = a - si * 3;
    double sc  = (si == 0) ? 32.0 : ((si == 1) ? 64.0 : 128.0);
    double rat = (ri == 0) ? 0.5  : ((ri == 1) ? 1.0  : 2.0);
    double w64 = sc * sqrt(1.0 / rat), h64 = sc * sqrt(rat);
    float cxs = ((float)x + 0.5f) * 4.f;
    float cys = ((float)y + 0.5f) * 4.f;
    float ax0 = cxs + (float)(-w64 * 0.5), ax2 = cxs + (float)(w64 * 0.5);
    float ay0 = cys + (float)(-h64 * 0.5), ay2 = cys + (float)(h64 * 0.5);
    float wa = ax2 - ax0, ha = ay2 - ay0;
    float cxa = ax0 + 0.5f * wa, cya = ay0 + 0.5f * ha;
    const float* dp = g_reg + (size_t)cell * 36 + a * 4;
    float d0 = dp[0], d1 = dp[1], d2 = dp[2], d3 = dp[3];
    float cx = d0 * wa + cxa, cy = d1 * ha + cya;
    float bw = expf(d2) * wa, bh = expf(d3) * ha;
    float X0 = cx - 0.5f * bw, Y0 = cy - 0.5f * bh;
    float X1 = cx + 0.5f * bw, Y1 = cy + 0.5f * bh;
    X0 = fminf(fmaxf(X0, 0.f), IW); X1 = fminf(fmaxf(X1, 0.f), IW);
    Y0 = fminf(fmaxf(Y0, 0.f), IH); Y1 = fminf(fmaxf(Y1, 0.f), IH);
    g_boxes[t] = make_float4(X0, Y0, X1, Y1);
    if ((X1 - X0 >= 1.0f) && (Y1 - Y0 >= 1.0f))
        atomicOr(&g_validmask[t >> 6], 1ull << (t & 63));
}

// ---------------- NMS mask ----------------
__global__ void k_mask() {
    __shared__ float4 cb[64];
    int cbk = blockIdx.x, rbk = blockIdx.y;
    int cbase = cbk * 64, rbase = rbk * 64;
    int t = threadIdx.x;
    int c = cbase + t;
    cb[t] = (c < PRE_NMSN) ? g_boxes[c] : make_float4(0, 0, 0, 0);
    __syncthreads();
    int i = rbase + t;
    if (i >= PRE_NMSN) return;
    float4 a = g_boxes[i];
    float areaA = (a.z - a.x) * (a.w - a.y);
    ull bits = 0;
    int lim = min(64, PRE_NMSN - cbase);
    for (int j = 0; j < lim; j++) {
        if (cbase + j == i) continue;
        float4 b = cb[j];
        float lx = fmaxf(a.x, b.x), ly = fmaxf(a.y, b.y);
        float rx = fminf(a.z, b.z), ry = fminf(a.w, b.w);
        float w = fmaxf(rx - lx, 0.f), h = fmaxf(ry - ly, 0.f);
        float inter = w * h;
        float areaB = (b.z - b.x) * (b.w - b.y);
        float iou = inter / (areaA + areaB - inter + 1e-9f);
        if (iou > NMS_TH) bits |= 1ull << j;
    }
    g_mask[(size_t)i * MASKW + cbk] = bits;
}

// ---------------- serial greedy scan (1 warp, depth-8 prefetch ring) ----------------
__global__ void k_scan() {
    int lane = threadIdx.x;
    ull remv[3];
#pragma unroll
    for (int k = 0; k < 3; k++) {
        int w = lane * 3 + k;
        remv[k] = (w < MASKW) ? ~g_validmask[w] : ~0ull;
    }
    ull pf[8][3];
#pragma unroll
    for (int d = 0; d < 8; d++) {
        const ull* row = g_mask + (size_t)d * MASKW + lane * 3;
        pf[d][0] = row[0]; pf[d][1] = row[1]; pf[d][2] = row[2];
    }
    int cnt = 0;
    for (int i8 = 0; i8 < PRE_NMSN; i8 += 8) {
#pragma unroll
        for (int d = 0; d < 8; d++) {
            int i = i8 + d;
            int w = i >> 6;
            int owner = w / 3, wm = w - owner * 3;
            ull myw = (wm == 0) ? remv[0] : ((wm == 1) ? remv[1] : remv[2]);
            ull word = __shfl_sync(0xffffffffu, myw, owner);
            if (!((word >> (i & 63)) & 1ull)) {
                if (cnt < POST_NMSN) { if (lane == 0) g_keptIdx[cnt] = i; }
                cnt++;
                remv[0] |= pf[d][0]; remv[1] |= pf[d][1]; remv[2] |= pf[d][2];
            }
            int nx = i + 8;
            if (nx < PRE_NMSN) {
                const ull* row = g_mask + (size_t)nx * MASKW + lane * 3;
                pf[d][0] = row[0]; pf[d][1] = row[1]; pf[d][2] = row[2];
            }
        }
        if (cnt >= POST_NMSN) break;
    }
    if (lane == 0) g_keptCnt = (cnt > POST_NMSN) ? POST_NMSN : cnt;
}

// ---------------- output ----------------
__global__ void k_out(float4* __restrict__ out) {
    int r = blockIdx.x * 256 + threadIdx.x;
    if (r >= POST_NMSN) return;
    float4 v = make_float4(0, 0, 0, 0);
    if (r < g_keptCnt) v = g_boxes[g_keptIdx[r]];
    out[r] = v;
}

// ---------------- launch ----------------
extern "C" void kernel_launch(void* const* d_in, const int* in_sizes, int n_in,
                              void* d_out, int out_size) {
    const float* feature = (const float*)d_in[0];
    const float* w1      = (const float*)d_in[1];
    const float* b1      = (const float*)d_in[2];
    const float* w_cls   = (const float*)d_in[3];
    const float* b_cls   = (const float*)d_in[4];
    const float* w_reg   = (const float*)d_in[5];
    const float* b_reg   = (const float*)d_in[6];
    const int*   ih      = (const int*)d_in[7];
    const int*   iw      = (const int*)d_in[8];

    static bool attr_set = false;
    if (!attr_set) {
        cudaFuncSetAttribute(k_sort, cudaFuncAttributeMaxDynamicSharedMemorySize, 65536);
        attr_set = true;
    }

    k_init<<<1, 256>>>();
    k_repack<<<576, 1024>>>(w1);
    k_conv<<<dim3(213, 2), 256>>>(feature, b1);
    k_heads<<<213, 256>>>(w_cls, b_cls, w_reg, b_reg);
    for (int p = 0; p < 4; p++) {
        k_hist<<<232, 256>>>(p);
        k_resolve<<<1, 256>>>();
    }
    k_compact<<<232, 256>>>();
    k_sort<<<1, 1024, 65536>>>();
    k_decode<<<47, 128>>>(ih, iw);
    k_mask<<<dim3(94, 94), 64>>>();
    k_scan<<<1, 32>>>();
    k_out<<<4, 256>>>((float4*)d_out);
}

// round 17
// speedup vs baseline: 1.7501x; 1.1232x over previous
#include <cuda_runtime.h>
#include <cstdint>

typedef unsigned long long ull;

#define HH 200
#define WW 272
#define SP 54400
#define NANCH 489600
#define PRE_NMSN 6000
#define POST_NMSN 1000
#define CAND_MAX 8192
#define MASKW 96
#define NMS_TH 0.7f

// ---------------- scratch ----------------
__device__ float g_x[(size_t)256 * SP];
__device__ float g_wr[9 * 256 * 256];
__device__ float g_conf[NANCH];
__device__ float g_reg[(size_t)SP * 36];
__device__ unsigned g_hist[256];
__device__ unsigned g_prefix;
__device__ int g_krem;
__device__ int g_candCnt;
__device__ ull g_cand[CAND_MAX];
__device__ float4 g_boxes[PRE_NMSN];
__device__ ull g_validmask[MASKW];
__device__ ull g_mask[(size_t)PRE_NMSN * MASKW];
__device__ int g_keptIdx[POST_NMSN];
__device__ int g_keptCnt;

// ---------------- helpers ----------------
__device__ __forceinline__ ull ffma2(ull a, ull b, ull c) {
    ull d;
    asm("fma.rn.f32x2 %0, %1, %2, %3;" : "=l"(d) : "l"(a), "l"(b), "l"(c));
    return d;
}
__device__ __forceinline__ ull packdup(float x) {
    ull d; unsigned u = __float_as_uint(x);
    asm("mov.b64 %0, {%1, %1};" : "=l"(d) : "r"(u));
    return d;
}
__device__ __forceinline__ unsigned key32(float v) {
    unsigned b = __float_as_uint(v);
    return (b & 0x80000000u) ? ~b : (b | 0x80000000u);
}
__device__ __forceinline__ float read_dim(const int* p) {
    int v = *p;
    if (v > 0 && v < 1000000) return (float)v;
    return __int_as_float(v);
}

// ---------------- init ----------------
__global__ void k_init() {
    int tid = threadIdx.x;
    g_hist[tid] = 0;
    if (tid < MASKW) g_validmask[tid] = 0ull;
    if (tid == 0) { g_prefix = 0; g_krem = PRE_NMSN; g_candCnt = 0; g_keptCnt = 0; }
}

// ---------------- weight repack ----------------
__global__ void k_repack(const float* __restrict__ w1) {
    int i = blockIdx.x * 1024 + threadIdx.x;
    if (i >= 9 * 256 * 256) return;
    int co = i / 2304;
    int r = i - co * 2304;
    int c = r / 9;
    int kk = r - c * 9;
    g_wr[((kk << 8) + c) * 256 + co] = w1[i];
}

// ---------------- conv 3x3 + bias + relu ----------------
// Exact R8 compute mapping (256 thr, 8co x 8n as 4+4 at 64-offset), KCRS order
// k = c*9 + (ky*3+kx) ascending; one sequential fp32 chain per output.
// Only change vs R8: double-buffered smem -> 1 sync/stage.
__global__ void __launch_bounds__(256, 2) k_conv(const float* __restrict__ feat,
                                                 const float* __restrict__ bias) {
    __shared__ float As[2][8][128];
    __shared__ float Bs[2][8][128];
    const int tid = threadIdx.x;
    const int n0 = blockIdx.x * 128, co0 = blockIdx.y * 128;
    const int lr = tid >> 5;
    const int lc4 = (tid & 31) << 2;
    const int tca = (tid >> 4) << 2;
    const int tn4 = (tid & 15) << 2;

    int yy[4], xx[4], nn[4];
#pragma unroll
    for (int i = 0; i < 4; i++) {
        int n = n0 + lc4 + i;
        nn[i] = n; yy[i] = n / WW; xx[i] = n - yy[i] * WW;
    }

    ull acc[8][4];
#pragma unroll
    for (int j = 0; j < 8; j++)
#pragma unroll
        for (int p = 0; p < 4; p++) acc[j][p] = 0ull;

    float4 av; float bv[4];
#define CONV_LOAD(q) { \
    int kq = ((q) << 3) + lr; \
    int c = kq / 9; int kk = kq - c * 9; \
    int kd = kk / 3; int dy = kd - 1, dx = kk - kd * 3 - 1; \
    av = *(const float4*)(g_wr + ((kk << 8) + c) * 256 + co0 + lc4); \
    const float* fp = feat + (size_t)c * SP + dy * WW + dx; \
    _Pragma("unroll") \
    for (int i_ = 0; i_ < 4; i_++) { \
        bool ok = ((unsigned)(yy[i_] + dy) < (unsigned)HH) && ((unsigned)(xx[i_] + dx) < (unsigned)WW); \
        bv[i_] = ok ? fp[nn[i_]] : 0.f; \
    } }

    CONV_LOAD(0)
    {
        *(float4*)&As[0][lr][lc4] = av;
        Bs[0][lr][lc4 + 0] = bv[0]; Bs[0][lr][lc4 + 1] = bv[1];
        Bs[0][lr][lc4 + 2] = bv[2]; Bs[0][lr][lc4 + 3] = bv[3];
    }
    __syncthreads();

    for (int q = 0; q < 288; q++) {
        int s = q & 1;
        if (q < 287) CONV_LOAD(q + 1)
#pragma unroll
        for (int k8 = 0; k8 < 8; k8++) {
            float4 blo = *(const float4*)&Bs[s][k8][tn4];
            float4 bhi = *(const float4*)&Bs[s][k8][64 + tn4];
            ull b0 = ((const ull*)&blo)[0], b1 = ((const ull*)&blo)[1];
            ull b2 = ((const ull*)&bhi)[0], b3 = ((const ull*)&bhi)[1];
            float4 a0 = *(const float4*)&As[s][k8][tca];
            float4 a1 = *(const float4*)&As[s][k8][64 + tca];
            float a[8] = {a0.x, a0.y, a0.z, a0.w, a1.x, a1.y, a1.z, a1.w};
#pragma unroll
            for (int j = 0; j < 8; j++) {
                ull aa = packdup(a[j]);
                acc[j][0] = ffma2(aa, b0, acc[j][0]);
                acc[j][1] = ffma2(aa, b1, acc[j][1]);
                acc[j][2] = ffma2(aa, b2, acc[j][2]);
                acc[j][3] = ffma2(aa, b3, acc[j][3]);
            }
        }
        if (q < 287) {
            int s2 = s ^ 1;
            *(float4*)&As[s2][lr][lc4] = av;
            Bs[s2][lr][lc4 + 0] = bv[0]; Bs[s2][lr][lc4 + 1] = bv[1];
            Bs[s2][lr][lc4 + 2] = bv[2]; Bs[s2][lr][lc4 + 3] = bv[3];
        }
        __syncthreads();
    }

#pragma unroll
    for (int j = 0; j < 8; j++) {
        int co = co0 + ((j < 4) ? (tca + j) : (64 + tca + j - 4));
        float bsv = bias[co];
        float o[8];
#pragma unroll
        for (int p = 0; p < 4; p++) {
            float lo = __uint_as_float((unsigned)(acc[j][p] & 0xffffffffull));
            float hi = __uint_as_float((unsigned)(acc[j][p] >> 32));
            o[2 * p]     = fmaxf(lo + bsv, 0.f);
            o[2 * p + 1] = fmaxf(hi + bsv, 0.f);
        }
        *(float4*)(g_x + (size_t)co * SP + n0 + tn4)      = make_float4(o[0], o[1], o[2], o[3]);
        *(float4*)(g_x + (size_t)co * SP + n0 + 64 + tn4) = make_float4(o[4], o[5], o[6], o[7]);
    }
}

// ---------------- 1x1 heads + fused radix pass 0 ----------------
__global__ void __launch_bounds__(256) k_heads(const float* __restrict__ wc,
                                               const float* __restrict__ bc,
                                               const float* __restrict__ wr,
                                               const float* __restrict__ br) {
    __shared__ float ws[45 * 256];
    __shared__ float bs[45];
    __shared__ unsigned shh[256];
    int tid = threadIdx.x;
    for (int i = tid; i < 45 * 256; i += 256) {
        int o = i >> 8, c = i & 255;
        ws[i] = (o < 9) ? wc[o * 256 + c] : wr[(o - 9) * 256 + c];
    }
    if (tid < 45) bs[tid] = (tid < 9) ? bc[tid] : br[tid - 9];
    shh[tid] = 0;
    __syncthreads();
    int n = blockIdx.x * 256 + tid;
    bool act = (n < SP);
    if (act) {
        float a[45];
#pragma unroll
        for (int o = 0; o < 45; o++) a[o] = 0.f;
        for (int c0 = 0; c0 < 256; c0 += 8) {
            float xv[8];
#pragma unroll
            for (int u = 0; u < 8; u++)
                xv[u] = g_x[(size_t)(c0 + u) * SP + n];
#pragma unroll
            for (int o = 0; o < 45; o++) {
                float4 w0 = *(const float4*)&ws[o * 256 + c0];
                float4 w1 = *(const float4*)&ws[o * 256 + c0 + 4];
                a[o] += w0.x * xv[0]; a[o] += w0.y * xv[1];
                a[o] += w0.z * xv[2]; a[o] += w0.w * xv[3];
                a[o] += w1.x * xv[4]; a[o] += w1.y * xv[5];
                a[o] += w1.z * xv[6]; a[o] += w1.w * xv[7];
            }
        }
#pragma unroll
        for (int o = 0; o < 9; o++) {
            float cf = a[o] + bs[o];
            g_conf[n * 9 + o] = cf;
            atomicAdd(&shh[key32(cf) >> 24], 1u);
        }
#pragma unroll
        for (int o = 0; o < 36; o++) g_reg[(size_t)n * 36 + o] = a[9 + o] + bs[9 + o];
    }
    __syncthreads();
    if (shh[tid]) atomicAdd(&g_hist[tid], shh[tid]);
}

// ---------------- radix select (passes 1..3) ----------------
__global__ void k_hist(int pass) {
    __shared__ unsigned sh[256];
    int tid = threadIdx.x;
    sh[tid] = 0;
    __syncthreads();
    unsigned pref = g_prefix;
    int sD = 24 - 8 * pass;
    for (int i = blockIdx.x * 256 + tid; i < NANCH; i += gridDim.x * 256) {
        unsigned k = key32(g_conf[i]);
        bool part = (pass == 0) || ((k >> (sD + 8)) == pref);
        if (part) atomicAdd(&sh[(k >> sD) & 255u], 1u);
    }
    __syncthreads();
    if (sh[tid]) atomicAdd(&g_hist[tid], sh[tid]);
}

__global__ void k_resolve() {
    __shared__ unsigned sh[256];
    int tid = threadIdx.x;
    sh[tid] = g_hist[tid];
    g_hist[tid] = 0;
    __syncthreads();
    if (tid == 0) {
        unsigned krem = (unsigned)g_krem;
        unsigned cum = 0; int d = 255;
        for (; d > 0; d--) {
            unsigned c = sh[d];
            if (cum + c >= krem) break;
            cum += c;
        }
        g_prefix = (g_prefix << 8) | (unsigned)d;
        g_krem = (int)(krem - cum);
    }
}

__global__ void k_compact() {
    unsigned T = g_prefix;
    for (int i = blockIdx.x * 256 + threadIdx.x; i < NANCH; i += gridDim.x * 256) {
        unsigned k = key32(g_conf[i]);
        if (k >= T) {
            int p = atomicAdd(&g_candCnt, 1);
            if (p < CAND_MAX) g_cand[p] = ((ull)k << 32) | (ull)(0xFFFFFFFFu - (unsigned)i);
        }
    }
}

// ---------------- bitonic sort desc in smem ----------------
__global__ void k_sort() {
    extern __shared__ ull s[];
    int tid = threadIdx.x;
    int cnt = g_candCnt; if (cnt > CAND_MAX) cnt = CAND_MAX;
    for (int i = tid; i < CAND_MAX; i += 1024) s[i] = (i < cnt) ? g_cand[i] : 0ull;
    __syncthreads();
    for (int k = 2; k <= CAND_MAX; k <<= 1) {
        for (int j = k >> 1; j > 0; j >>= 1) {
            for (int i = tid; i < CAND_MAX; i += 1024) {
                int ixj = i ^ j;
                if (ixj > i) {
                    ull A = s[i], B = s[ixj];
                    bool desc = ((i & k) == 0);
                    if (desc ? (A < B) : (A > B)) { s[i] = B; s[ixj] = A; }
                }
            }
            __syncthreads();
        }
    }
    for (int i = tid; i < CAND_MAX; i += 1024) g_cand[i] = s[i];
}

// ---------------- decode + clip + min-size ----------------
__global__ void k_decode(const int* __restrict__ ph, const int* __restrict__ pw) {
    int t = blockIdx.x * 128 + threadIdx.x;
    if (t >= PRE_NMSN) return;
    float IW = read_dim(pw), IH = read_dim(ph);
    ull cd = g_cand[t];
    unsigned orig = 0xFFFFFFFFu - (unsigned)(cd & 0xFFFFFFFFull);
    if (orig >= NANCH) { g_boxes[t] = make_float4(0, 0, 0, 0); return; }
    int cell = orig / 9; int a = orig - cell * 9;
    int y = cell / WW;   int x = cell - y * WW;
    int si = a / 3;      int ri = a - si * 3;
    double sc  = (si == 0) ? 32.0 : ((si == 1) ? 64.0 : 128.0);
    double rat = (ri == 0) ? 0.5  : ((ri == 1) ? 1.0  : 2.0);
    double w64 = sc * sqrt(1.0 / rat), h64 = sc * sqrt(rat);
    float cxs = ((float)x + 0.5f) * 4.f;
    float cys = ((float)y + 0.5f) * 4.f;
    float ax0 = cxs + (float)(-w64 * 0.5), ax2 = cxs + (float)(w64 * 0.5);
    float ay0 = cys + (float)(-h64 * 0.5), ay2 = cys + (float)(h64 * 0.5);
    float wa = ax2 - ax0, ha = ay2 - ay0;
    float cxa = ax0 + 0.5f * wa, cya = ay0 + 0.5f * ha;
    const float* dp = g_reg + (size_t)cell * 36 + a * 4;
    float d0 = dp[0], d1 = dp[1], d2 = dp[2], d3 = dp[3];
    float cx = d0 * wa + cxa, cy = d1 * ha + cya;
    float bw = expf(d2) * wa, bh = expf(d3) * ha;
    float X0 = cx - 0.5f * bw, Y0 = cy - 0.5f * bh;
    float X1 = cx + 0.5f * bw, Y1 = cy + 0.5f * bh;
    X0 = fminf(fmaxf(X0, 0.f), IW); X1 = fminf(fmaxf(X1, 0.f), IW);
    Y0 = fminf(fmaxf(Y0, 0.f), IH); Y1 = fminf(fmaxf(Y1, 0.f), IH);
    g_boxes[t] = make_float4(X0, Y0, X1, Y1);
    if ((X1 - X0 >= 1.0f) && (Y1 - Y0 >= 1.0f))
        atomicOr(&g_validmask[t >> 6], 1ull << (t & 63));
}

// ---------------- NMS mask ----------------
__global__ void k_mask() {
    __shared__ float4 cb[64];
    int cbk = blockIdx.x, rbk = blockIdx.y;
    int cbase = cbk * 64, rbase = rbk * 64;
    int t = threadIdx.x;
    int c = cbase + t;
    cb[t] = (c < PRE_NMSN) ? g_boxes[c] : make_float4(0, 0, 0, 0);
    __syncthreads();
    int i = rbase + t;
    if (i >= PRE_NMSN) return;
    float4 a = g_boxes[i];
    float areaA = (a.z - a.x) * (a.w - a.y);
    ull bits = 0;
    int lim = min(64, PRE_NMSN - cbase);
    for (int j = 0; j < lim; j++) {
        if (cbase + j == i) continue;
        float4 b = cb[j];
        float lx = fmaxf(a.x, b.x), ly = fmaxf(a.y, b.y);
        float rx = fminf(a.z, b.z), ry = fminf(a.w, b.w);
        float w = fmaxf(rx - lx, 0.f), h = fmaxf(ry - ly, 0.f);
        float inter = w * h;
        float areaB = (b.z - b.x) * (b.w - b.y);
        float iou = inter / (areaA + areaB - inter + 1e-9f);
        if (iou > NMS_TH) bits |= 1ull << j;
    }
    g_mask[(size_t)i * MASKW + cbk] = bits;
}

// ---------------- serial greedy scan (1 warp, depth-8 prefetch ring) ----------------
__global__ void k_scan() {
    int lane = threadIdx.x;
    ull remv[3];
#pragma unroll
    for (int k = 0; k < 3; k++) {
        int w = lane * 3 + k;
        remv[k] = (w < MASKW) ? ~g_validmask[w] : ~0ull;
    }
    ull pf[8][3];
#pragma unroll
    for (int d = 0; d < 8; d++) {
        const ull* row = g_mask + (size_t)d * MASKW + lane * 3;
        pf[d][0] = row[0]; pf[d][1] = row[1]; pf[d][2] = row[2];
    }
    int cnt = 0;
    for (int i8 = 0; i8 < PRE_NMSN; i8 += 8) {
#pragma unroll
        for (int d = 0; d < 8; d++) {
            int i = i8 + d;
            int w = i >> 6;
            int owner = w / 3, wm = w - owner * 3;
            ull myw = (wm == 0) ? remv[0] : ((wm == 1) ? remv[1] : remv[2]);
            ull word = __shfl_sync(0xffffffffu, myw, owner);
            if (!((word >> (i & 63)) & 1ull)) {
                if (cnt < POST_NMSN) { if (lane == 0) g_keptIdx[cnt] = i; }
                cnt++;
                remv[0] |= pf[d][0]; remv[1] |= pf[d][1]; remv[2] |= pf[d][2];
            }
            int nx = i + 8;
            if (nx < PRE_NMSN) {
                const ull* row = g_mask + (size_t)nx * MASKW + lane * 3;
                pf[d][0] = row[0]; pf[d][1] = row[1]; pf[d][2] = row[2];
            }
        }
        if (cnt >= POST_NMSN) break;
    }
    if (lane == 0) g_keptCnt = (cnt > POST_NMSN) ? POST_NMSN : cnt;
}

// ---------------- output ----------------
__global__ void k_out(float4* __restrict__ out) {
    int r = blockIdx.x * 256 + threadIdx.x;
    if (r >= POST_NMSN) return;
    float4 v = make_float4(0, 0, 0, 0);
    if (r < g_keptCnt) v = g_boxes[g_keptIdx[r]];
    out[r] = v;
}

// ---------------- launch ----------------
extern "C" void kernel_launch(void* const* d_in, const int* in_sizes, int n_in,
                              void* d_out, int out_size) {
    const float* feature = (const float*)d_in[0];
    const float* w1      = (const float*)d_in[1];
    const float* b1      = (const float*)d_in[2];
    const float* w_cls   = (const float*)d_in[3];
    const float* b_cls   = (const float*)d_in[4];
    const float* w_reg   = (const float*)d_in[5];
    const float* b_reg   = (const float*)d_in[6];
    const int*   ih      = (const int*)d_in[7];
    const int*   iw      = (const int*)d_in[8];

    static bool attr_set = false;
    if (!attr_set) {
        cudaFuncSetAttribute(k_sort, cudaFuncAttributeMaxDynamicSharedMemorySize, 65536);
        attr_set = true;
    }

    k_init<<<1, 256>>>();
    k_repack<<<576, 1024>>>(w1);
    k_conv<<<dim3(425, 2), 256>>>(feature, b1);
    k_heads<<<213, 256>>>(w_cls, b_cls, w_reg, b_reg);   // includes radix pass 0
    k_resolve<<<1, 256>>>();
    for (int p = 1; p < 4; p++) {
        k_hist<<<232, 256>>>(p);
        k_resolve<<<1, 256>>>();
    }
    k_compact<<<232, 256>>>();
    k_sort<<<1, 1024, 65536>>>();
    k_decode<<<47, 128>>>(ih, iw);
    k_mask<<<dim3(94, 94), 64>>>();
    k_scan<<<1, 32>>>();
    k_out<<<4, 256>>>((float4*)d_out);
}